// round 14
// baseline (speedup 1.0000x reference)
#include <cuda_runtime.h>
#include <cub/cub.cuh>

// ---------------------------------------------------------------------------
// Graph U-Net forward — level-0 CSR only; virtual pooled traversal; PDL;
// 4-wide (int4) edge processing in hist/scatter for MLP.
// ---------------------------------------------------------------------------
#define cN0 80000
#define cN1 40000
#define cN2 20000
#define cN3 10000
#define cNE 1280000
#define HID 64
#define BN_EPS 1e-5f
#define TPB 256
#define GRIDE4 1250   // ceil((cNE/4) / TPB)
#define FULLM 0xffffffffu

// ------------------------- static device scratch ---------------------------
__device__ __align__(16) float g_X0[cN0 * HID];
__device__ __align__(16) float g_X1[cN1 * HID];
__device__ __align__(16) float g_X2[cN2 * HID];
__device__ __align__(16) float g_H [cN0 * HID];
__device__ __align__(16) float g_Y [cN0 * HID];
__device__ __align__(16) float g_YD3[cN3 * HID];
__device__ __align__(16) float g_YU0[cN2 * HID];
__device__ __align__(16) float g_YU1[cN1 * HID];
__device__ int   g_deg[cN0 + 1];
__device__ int   g_cursor[cN0];
__device__ int   g_rs0[cN0 + 1];
__device__ int   g_csr0[cNE];
__device__ float g_dinv0_2[cN0], g_dinv0_1[cN0];
__device__ float g_dinv1[cN1], g_dinv2[cN2], g_dinv3[cN3];
__device__ float g_keys[cN0], g_keysOut[cN0];
__device__ int   g_idx[cN0];
__device__ int   g_perm0[cN0], g_perm1[cN1], g_perm2[cN2];
__device__ int   g_O2[cN2], g_O3[cN3];
__device__ int   g_M1[cN0], g_M2[cN0], g_M3[cN0];
__device__ float g_statsAll[6 * 128];
__device__ float g_h1[cN0];
__device__ __align__(256) unsigned char g_cubtmp[16 * 1024 * 1024];

// ------------------------------- kernels -----------------------------------
__global__ void k_zero_deg_stats(int* __restrict__ deg, float* __restrict__ stats0, int n) {
    int t = blockIdx.x * blockDim.x + threadIdx.x;
    if (t < n) deg[t] = 0;
    if (t < 128) stats0[t] = 0.f;
}

// 4 edges per thread: independent atomics raise MLP
__global__ void k_hist0(const int* __restrict__ dst, int* __restrict__ deg) {
    cudaGridDependencySynchronize();
    int t = blockIdx.x * blockDim.x + threadIdx.x;
    if (t >= cNE / 4) return;
    int4 d4 = reinterpret_cast<const int4*>(dst)[t];
    atomicAdd(&deg[d4.x], 1);
    atomicAdd(&deg[d4.y], 1);
    atomicAdd(&deg[d4.z], 1);
    atomicAdd(&deg[d4.w], 1);
}

__global__ void k_prep(const int* __restrict__ rs, int* __restrict__ cursor,
                       float* __restrict__ dinvA, float fillA,
                       float* __restrict__ dinvB, float fillB, int n) {
    cudaGridDependencySynchronize();
    int t = blockIdx.x * blockDim.x + threadIdx.x;
    if (t >= n) return;
    int r0 = rs[t], r1 = rs[t + 1];
    cursor[t] = r0;
    float d = (float)(r1 - r0);
    dinvA[t] = rsqrtf(d + fillA);
    if (dinvB) dinvB[t] = rsqrtf(d + fillB);
}

// 4 edges per thread: 4 independent atomic+store chains in flight
__global__ void k_scatter(const int* __restrict__ srcC, const int* __restrict__ dstC,
                          int* __restrict__ cursor, int* __restrict__ csr) {
    cudaGridDependencySynchronize();
    int t = blockIdx.x * blockDim.x + threadIdx.x;
    if (t >= cNE / 4) return;
    int4 s4 = reinterpret_cast<const int4*>(srcC)[t];
    int4 d4 = reinterpret_cast<const int4*>(dstC)[t];
    int p0 = atomicAdd(&cursor[d4.x], 1);
    int p1 = atomicAdd(&cursor[d4.y], 1);
    int p2 = atomicAdd(&cursor[d4.z], 1);
    int p3 = atomicAdd(&cursor[d4.w], 1);
    csr[p0] = s4.x;
    csr[p1] = s4.y;
    csr[p2] = s4.z;
    csr[p3] = s4.w;
}

__global__ void k_mapset_v(const int* __restrict__ perm, const int* __restrict__ origPrev,
                           int* __restrict__ origOut, int* __restrict__ map, int k) {
    int t = blockIdx.x * blockDim.x + threadIdx.x;
    if (t >= k) return;
    int o = origPrev ? origPrev[perm[t]] : perm[t];
    if (origOut) origOut[t] = o;
    map[o] = t;
}

__global__ void k_degdinv(const int* __restrict__ rs, const int* __restrict__ csr,
                          const int* __restrict__ orig, const int* __restrict__ map,
                          float* __restrict__ dinv, int k) {
    cudaGridDependencySynchronize();
    int lane = threadIdx.x & 31;
    int w = (blockIdx.x * blockDim.x + threadIdx.x) >> 5;
    int nw = (gridDim.x * blockDim.x) >> 5;
    for (int d = w; d < k; d += nw) {
        int o = orig[d];
        int r0 = rs[o], r1 = rs[o + 1];
        int cnt = 0;
        for (int j = r0 + lane; j < r1; j += 32)
            cnt += (map[csr[j]] >= 0) ? 1 : 0;
        #pragma unroll
        for (int off = 16; off > 0; off >>= 1) cnt += __shfl_xor_sync(FULLM, cnt, off);
        if (lane == 0) dinv[d] = rsqrtf((float)cnt + 2.0f);
    }
}

// block 0 fused: 3-channel aggregate over csr0, then 3->64 matmul + BN stats
__global__ void k_agg3_bn(const int* __restrict__ rs, const int* __restrict__ csr,
                          const float* __restrict__ dinv, const float* __restrict__ x,
                          const float* __restrict__ W, float* __restrict__ Y,
                          float* __restrict__ stats, int n) {
    __shared__ float sh[128];
    if (threadIdx.x < 128) sh[threadIdx.x] = 0.f;
    int lane = threadIdx.x & 31;
    float w00 = __ldg(&W[2 * lane]),           w01 = __ldg(&W[2 * lane + 1]);
    float w10 = __ldg(&W[HID + 2 * lane]),     w11 = __ldg(&W[HID + 2 * lane + 1]);
    float w20 = __ldg(&W[2 * HID + 2 * lane]), w21 = __ldg(&W[2 * HID + 2 * lane + 1]);
    cudaGridDependencySynchronize();
    __syncthreads();
    int w = (blockIdx.x * blockDim.x + threadIdx.x) >> 5;
    int nw = (gridDim.x * blockDim.x) >> 5;
    float s0 = 0.f, s1 = 0.f, q0 = 0.f, q1 = 0.f;
    for (int d = w; d < n; d += nw) {
        int r0 = rs[d], r1 = rs[d + 1];
        float ax = 0.f, ay = 0.f, az = 0.f;
        for (int j = r0 + lane; j < r1; j += 32) {
            int s = csr[j];
            float ds = dinv[s];
            const float* xs = x + 3 * (long long)s;
            ax += ds * xs[0];
            ay += ds * xs[1];
            az += ds * xs[2];
        }
        #pragma unroll
        for (int o = 16; o > 0; o >>= 1) {
            ax += __shfl_xor_sync(FULLM, ax, o);
            ay += __shfl_xor_sync(FULLM, ay, o);
            az += __shfl_xor_sync(FULLM, az, o);
        }
        float dd = dinv[d];
        float sf = 2.0f * dd * dd;
        const float* xd = x + 3 * (long long)d;
        float b0 = dd * ax + sf * xd[0];
        float b1 = dd * ay + sf * xd[1];
        float b2 = dd * az + sf * xd[2];
        float y0 = b0 * w00 + b1 * w10 + b2 * w20;
        float y1 = b0 * w01 + b1 * w11 + b2 * w21;
        reinterpret_cast<float2*>(Y)[(long long)d * 32 + lane] = make_float2(y0, y1);
        s0 += y0; s1 += y1; q0 += y0 * y0; q1 += y1 * y1;
    }
    atomicAdd(&sh[2 * lane],      s0);
    atomicAdd(&sh[2 * lane + 1],  s1);
    atomicAdd(&sh[64 + 2 * lane], q0);
    atomicAdd(&sh[65 + 2 * lane], q1);
    __syncthreads();
    if (threadIdx.x < 128) atomicAdd(&stats[threadIdx.x], sh[threadIdx.x]);
}

__global__ void k_mm_pool(const float* __restrict__ X, const float* __restrict__ W,
                          const int* __restrict__ perm, const float* __restrict__ sc,
                          float* __restrict__ H, float* __restrict__ stats, int n) {
    __shared__ float sW[HID * HID];
    for (int i = threadIdx.x; i < HID * HID; i += blockDim.x) sW[i] = W[i];
    cudaGridDependencySynchronize();
    if (blockIdx.x == 0 && threadIdx.x < 128) stats[threadIdx.x] = 0.f;
    __syncthreads();
    int t = blockIdx.x * blockDim.x + threadIdx.x;
    int rg = t >> 4, cg = t & 15;
    if (rg * 4 >= n) return;
    const float* xp[4];
    float s[4];
    #pragma unroll
    for (int i = 0; i < 4; i++) {
        int r = rg * 4 + i;
        xp[i] = X + (long long)perm[r] * HID;
        s[i] = sc[r];
    }
    float acc[4][4];
    #pragma unroll
    for (int i = 0; i < 4; i++)
        #pragma unroll
        for (int j = 0; j < 4; j++) acc[i][j] = 0.f;
    for (int k = 0; k < HID; k++) {
        float4 w = reinterpret_cast<const float4*>(sW)[k * 16 + cg];
        #pragma unroll
        for (int i = 0; i < 4; i++) {
            float xv = xp[i][k] * s[i];
            acc[i][0] += xv * w.x; acc[i][1] += xv * w.y;
            acc[i][2] += xv * w.z; acc[i][3] += xv * w.w;
        }
    }
    #pragma unroll
    for (int i = 0; i < 4; i++)
        reinterpret_cast<float4*>(H)[(long long)(rg * 4 + i) * 16 + cg] =
            make_float4(acc[i][0], acc[i][1], acc[i][2], acc[i][3]);
}

__global__ void k_vagg_bn(const int* __restrict__ rs, const int* __restrict__ csr,
                          const int* __restrict__ orig, const int* __restrict__ map,
                          const float* __restrict__ dinv, const float* __restrict__ H,
                          float* __restrict__ Y, float* __restrict__ stats, int n) {
    __shared__ float sh[128];
    if (threadIdx.x < 128) sh[threadIdx.x] = 0.f;
    cudaGridDependencySynchronize();
    __syncthreads();
    int lane = threadIdx.x & 31;
    int w = (blockIdx.x * blockDim.x + threadIdx.x) >> 5;
    int nw = (gridDim.x * blockDim.x) >> 5;
    float s0 = 0.f, s1 = 0.f, q0 = 0.f, q1 = 0.f;
    for (int d = w; d < n; d += nw) {
        int o = orig[d];
        int r0 = rs[o], r1 = rs[o + 1];
        float dd = dinv[d];
        float a0 = 0.f, a1 = 0.f;
        int j = r0;
        for (; j + 2 <= r1; j += 2) {
            int cA = map[csr[j]];
            int cB = map[csr[j + 1]];
            if (cA >= 0) {
                float cf = dinv[cA] * dd;
                float2 h = reinterpret_cast<const float2*>(H)[(long long)cA * 32 + lane];
                a0 += cf * h.x; a1 += cf * h.y;
            }
            if (cB >= 0) {
                float cf = dinv[cB] * dd;
                float2 h = reinterpret_cast<const float2*>(H)[(long long)cB * 32 + lane];
                a0 += cf * h.x; a1 += cf * h.y;
            }
        }
        if (j < r1) {
            int cA = map[csr[j]];
            if (cA >= 0) {
                float cf = dinv[cA] * dd;
                float2 h = reinterpret_cast<const float2*>(H)[(long long)cA * 32 + lane];
                a0 += cf * h.x; a1 += cf * h.y;
            }
        }
        float2 hd = reinterpret_cast<const float2*>(H)[(long long)d * 32 + lane];
        float sf = 2.0f * dd * dd;
        float y0 = a0 + sf * hd.x;
        float y1 = a1 + sf * hd.y;
        reinterpret_cast<float2*>(Y)[(long long)d * 32 + lane] = make_float2(y0, y1);
        s0 += y0; s1 += y1; q0 += y0 * y0; q1 += y1 * y1;
    }
    atomicAdd(&sh[2 * lane],      s0);
    atomicAdd(&sh[2 * lane + 1],  s1);
    atomicAdd(&sh[64 + 2 * lane], q0);
    atomicAdd(&sh[65 + 2 * lane], q1);
    __syncthreads();
    if (threadIdx.x < 128) atomicAdd(&stats[threadIdx.x], sh[threadIdx.x]);
}

__global__ void k_bn_score(const float* __restrict__ Y, const float* __restrict__ gamma,
                           const float* __restrict__ beta, const float* __restrict__ stats,
                           float* __restrict__ Xo, const float* __restrict__ pw,
                           float* __restrict__ keys, int* __restrict__ idx,
                           int* __restrict__ map, int nMapInit, int n) {
    int gtid = blockIdx.x * blockDim.x + threadIdx.x;
    int stride = gridDim.x * blockDim.x;
    int lane = threadIdx.x & 31;
    float inv_n = 1.f / (float)n;
    float pa = pw[lane], pb = pw[lane + 32];
    float g0 = gamma[lane], g1 = gamma[lane + 32];
    float be0 = beta[lane], be1 = beta[lane + 32];
    float nv = pa * pa + pb * pb;
    #pragma unroll
    for (int o = 16; o > 0; o >>= 1) nv += __shfl_xor_sync(FULLM, nv, o);
    float rn = rsqrtf(nv);
    cudaGridDependencySynchronize();
    float mu0 = stats[lane] * inv_n;
    float var0 = stats[HID + lane] * inv_n - mu0 * mu0;
    float rsA = g0 * rsqrtf(var0 + BN_EPS);
    float mu1 = stats[lane + 32] * inv_n;
    float var1 = stats[HID + lane + 32] * inv_n - mu1 * mu1;
    float rsB = g1 * rsqrtf(var1 + BN_EPS);
    for (int r = gtid >> 5; r < n; r += stride >> 5) {
        float y0 = Y[(long long)r * HID + lane];
        float y1 = Y[(long long)r * HID + lane + 32];
        float x0 = fmaxf(rsA * (y0 - mu0) + be0, 0.f);
        float x1 = fmaxf(rsB * (y1 - mu1) + be1, 0.f);
        Xo[(long long)r * HID + lane] = x0;
        Xo[(long long)r * HID + lane + 32] = x1;
        float v = x0 * pa + x1 * pb;
        #pragma unroll
        for (int o = 16; o > 0; o >>= 1) v += __shfl_xor_sync(FULLM, v, o);
        if (lane == 0) {
            keys[r] = fmaxf(v * rn, 0.f);
            idx[r] = r;
        }
    }
    for (int t = gtid; t < nMapInit; t += stride) map[t] = -1;
}

__global__ void k_mm_res_bn(const float* __restrict__ X, const float* __restrict__ Yup,
                            const int* __restrict__ orig, const int* __restrict__ mapNext,
                            const float* __restrict__ gammaP, const float* __restrict__ betaP,
                            const float* __restrict__ statsP, float inv_np,
                            const float* __restrict__ W,
                            float* __restrict__ H, float* __restrict__ stats, int n) {
    __shared__ float sW[HID * HID];
    __shared__ float sA[HID], sB[HID];
    for (int i = threadIdx.x; i < HID * HID; i += blockDim.x) sW[i] = W[i];
    cudaGridDependencySynchronize();
    if (threadIdx.x < HID) {
        int c = threadIdx.x;
        float mu = statsP[c] * inv_np;
        float var = statsP[HID + c] * inv_np - mu * mu;
        float g = gammaP[c] * rsqrtf(var + BN_EPS);
        sA[c] = g;
        sB[c] = betaP[c] - g * mu;
    }
    if (blockIdx.x == 0 && threadIdx.x < 128) stats[threadIdx.x] = 0.f;
    __syncthreads();
    int t = blockIdx.x * blockDim.x + threadIdx.x;
    int rg = t >> 4, cg = t & 15;
    if (rg * 4 >= n) return;
    const float* xp[4];
    const float* up[4];
    #pragma unroll
    for (int i = 0; i < 4; i++) {
        int r = rg * 4 + i;
        xp[i] = X + (long long)r * HID;
        int m = mapNext[orig ? orig[r] : r];
        up[i] = (m >= 0) ? (Yup + (long long)m * HID) : nullptr;
    }
    float acc[4][4];
    #pragma unroll
    for (int i = 0; i < 4; i++)
        #pragma unroll
        for (int j = 0; j < 4; j++) acc[i][j] = 0.f;
    for (int k = 0; k < HID; k++) {
        float4 wv = reinterpret_cast<const float4*>(sW)[k * 16 + cg];
        float a = sA[k], b = sB[k];
        #pragma unroll
        for (int i = 0; i < 4; i++) {
            float xv = xp[i][k];
            if (up[i]) xv += fmaxf(a * up[i][k] + b, 0.f);
            acc[i][0] += xv * wv.x; acc[i][1] += xv * wv.y;
            acc[i][2] += xv * wv.z; acc[i][3] += xv * wv.w;
        }
    }
    #pragma unroll
    for (int i = 0; i < 4; i++)
        reinterpret_cast<float4*>(H)[(long long)(rg * 4 + i) * 16 + cg] =
            make_float4(acc[i][0], acc[i][1], acc[i][2], acc[i][3]);
}

__global__ void k_mm1_res_bn(const float* __restrict__ X, const float* __restrict__ Yup,
                             const int* __restrict__ mapNext,
                             const float* __restrict__ gammaP, const float* __restrict__ betaP,
                             const float* __restrict__ statsP, float inv_np,
                             const float* __restrict__ W, float* __restrict__ h, int n) {
    __shared__ float sW[HID], sA[HID], sB[HID];
    cudaGridDependencySynchronize();
    if (threadIdx.x < HID) {
        int c = threadIdx.x;
        sW[c] = W[c];
        float mu = statsP[c] * inv_np;
        float var = statsP[HID + c] * inv_np - mu * mu;
        float g = gammaP[c] * rsqrtf(var + BN_EPS);
        sA[c] = g;
        sB[c] = betaP[c] - g * mu;
    }
    __syncthreads();
    int r = blockIdx.x * blockDim.x + threadIdx.x;
    if (r >= n) return;
    int m = mapNext[r];
    const float* xp = X + (long long)r * HID;
    const float* up = (m >= 0) ? (Yup + (long long)m * HID) : nullptr;
    float acc = 0.f;
    #pragma unroll
    for (int k = 0; k < HID; k++) {
        float xv = xp[k];
        if (up) xv += fmaxf(sA[k] * up[k] + sB[k], 0.f);
        acc += xv * sW[k];
    }
    h[r] = acc;
}

__global__ void k_csr_final(const int* __restrict__ rs, const int* __restrict__ csr,
                            const float* __restrict__ dinv, const float* __restrict__ h,
                            float* __restrict__ out, int n) {
    cudaGridDependencySynchronize();
    int lane = threadIdx.x & 31;
    int w = (blockIdx.x * blockDim.x + threadIdx.x) >> 5;
    int nw = (gridDim.x * blockDim.x) >> 5;
    for (int d = w; d < n; d += nw) {
        int r0 = rs[d], r1 = rs[d + 1];
        float acc = 0.f;
        for (int j = r0 + lane; j < r1; j += 32) {
            int s = csr[j];
            acc += dinv[s] * h[s];
        }
        #pragma unroll
        for (int o = 16; o > 0; o >>= 1) acc += __shfl_xor_sync(FULLM, acc, o);
        if (lane == 0) {
            float dd = dinv[d];
            float v = dd * acc + dd * dd * h[d];
            out[d] = 1.f / (1.f + expf(-v));
        }
    }
}

// ------------------------------- host side ---------------------------------
static inline int nblk(long long n) { return (int)((n + TPB - 1) / TPB); }
static inline int gridA(int n) { int g = (n + 7) / 8; return g > 2048 ? 2048 : g; }

template <typename... Args>
static void pdl(void (*kern)(Args...), int grid, int block, cudaStream_t st, Args... args) {
    cudaLaunchConfig_t cfg = {};
    cfg.gridDim = dim3(grid);
    cfg.blockDim = dim3(block);
    cfg.stream = st;
    cudaLaunchAttribute attr[1];
    attr[0].id = cudaLaunchAttributeProgrammaticStreamSerialization;
    attr[0].val.programmaticStreamSerializationAllowed = 1;
    cfg.attrs = attr;
    cfg.numAttrs = 1;
    cudaLaunchKernelEx(&cfg, kern, args...);
}

struct DevPtrs {
    float *X0, *X1, *X2, *H, *Y, *YD3, *YU0, *YU1;
    int *deg, *cursor, *rs0, *csr0;
    float *dinv0_2, *dinv0_1, *dinv1, *dinv2, *dinv3;
    float *keys, *keysOut, *stats, *h1;
    int *idx, *perm0, *perm1, *perm2, *O2, *O3, *M1, *M2, *M3;
    void* cubtmp;
};

#define GETP(sym, field, type) { void* q; cudaGetSymbolAddress(&q, sym); p.field = (type)q; }

static void get_ptrs(DevPtrs& p) {
    GETP(g_X0, X0, float*) GETP(g_X1, X1, float*) GETP(g_X2, X2, float*)
    GETP(g_H, H, float*) GETP(g_Y, Y, float*)
    GETP(g_YD3, YD3, float*) GETP(g_YU0, YU0, float*) GETP(g_YU1, YU1, float*)
    GETP(g_deg, deg, int*) GETP(g_cursor, cursor, int*)
    GETP(g_rs0, rs0, int*) GETP(g_csr0, csr0, int*)
    GETP(g_dinv0_2, dinv0_2, float*) GETP(g_dinv0_1, dinv0_1, float*)
    GETP(g_dinv1, dinv1, float*) GETP(g_dinv2, dinv2, float*) GETP(g_dinv3, dinv3, float*)
    GETP(g_keys, keys, float*) GETP(g_keysOut, keysOut, float*)
    GETP(g_statsAll, stats, float*) GETP(g_h1, h1, float*)
    GETP(g_idx, idx, int*)
    GETP(g_perm0, perm0, int*) GETP(g_perm1, perm1, int*) GETP(g_perm2, perm2, int*)
    GETP(g_O2, O2, int*) GETP(g_O3, O3, int*)
    GETP(g_M1, M1, int*) GETP(g_M2, M2, int*) GETP(g_M3, M3, int*)
    GETP(g_cubtmp, cubtmp, void*)
}

static cudaStream_t s_side;
static cudaEvent_t  s_evF[3], s_evJ[3];
static bool s_init = false;

static void fork_side(int i) {
    cudaEventRecord(s_evF[i], 0);
    cudaStreamWaitEvent(s_side, s_evF[i], 0);
}
static void join_side(int i) {
    cudaEventRecord(s_evJ[i], s_side);
    cudaStreamWaitEvent(0, s_evJ[i], 0);
}

static void radix_sort(const DevPtrs& p, int* permOut, int n) {
    size_t tb = 0;
    cub::DeviceRadixSort::SortPairsDescending(nullptr, tb, p.keys, p.keysOut,
                                              p.idx, permOut, n, 0, 32, (cudaStream_t)0);
    cub::DeviceRadixSort::SortPairsDescending(p.cubtmp, tb, p.keys, p.keysOut,
                                              p.idx, permOut, n, 0, 32, (cudaStream_t)0);
}

extern "C" void kernel_launch(void* const* d_in, const int* in_sizes, int n_in,
                              void* d_out, int out_size) {
    if (!s_init) {   // first call is the uncaptured correctness run
        cudaStreamCreateWithFlags(&s_side, cudaStreamNonBlocking);
        for (int i = 0; i < 3; i++) {
            cudaEventCreateWithFlags(&s_evF[i], cudaEventDisableTiming);
            cudaEventCreateWithFlags(&s_evJ[i], cudaEventDisableTiming);
        }
        s_init = true;
    }

    const float* x_in = (const float*)d_in[0];
    const int* ei     = (const int*)d_in[1];
    const int* src0 = ei;
    const int* dst0 = ei + cNE;
    const float* Wd[4] = {(const float*)d_in[2],  (const float*)d_in[5],
                          (const float*)d_in[8],  (const float*)d_in[11]};
    const float* gd[4] = {(const float*)d_in[3],  (const float*)d_in[6],
                          (const float*)d_in[9],  (const float*)d_in[12]};
    const float* bd[4] = {(const float*)d_in[4],  (const float*)d_in[7],
                          (const float*)d_in[10], (const float*)d_in[13]};
    const float* pw[3] = {(const float*)d_in[14], (const float*)d_in[15],
                          (const float*)d_in[16]};
    const float* Wu[2] = {(const float*)d_in[17], (const float*)d_in[20]};
    const float* gu[2] = {(const float*)d_in[18], (const float*)d_in[21]};
    const float* bu[2] = {(const float*)d_in[19], (const float*)d_in[22]};
    const float* Wout  = (const float*)d_in[23];

    DevPtrs p;
    get_ptrs(p);
    float* S[6];
    for (int i = 0; i < 6; i++) S[i] = p.stats + i * 128;
    cudaStream_t s0 = 0;

    // ===== level 0: CSR build + fused agg3+mm+BNstats =====
    k_zero_deg_stats<<<nblk(cN0 + 1), TPB>>>(p.deg, S[0], cN0 + 1);
    pdl(k_hist0, GRIDE4, TPB, s0, dst0, p.deg);
    {
        size_t tb = 0;
        cub::DeviceScan::ExclusiveSum(nullptr, tb, p.deg, p.rs0, cN0 + 1, (cudaStream_t)0);
        cub::DeviceScan::ExclusiveSum(p.cubtmp, tb, p.deg, p.rs0, cN0 + 1, (cudaStream_t)0);
    }
    pdl(k_prep, nblk(cN0), TPB, s0, (const int*)p.rs0, p.cursor,
        p.dinv0_2, 2.0f, p.dinv0_1, 1.0f, cN0);
    pdl(k_scatter, GRIDE4, TPB, s0, src0, dst0, p.cursor, p.csr0);
    pdl(k_agg3_bn, gridA(cN0), TPB, s0, (const int*)p.rs0, (const int*)p.csr0,
        (const float*)p.dinv0_2, x_in, Wd[0], p.Y, S[0], cN0);
    pdl(k_bn_score, 2048, TPB, s0, (const float*)p.Y, gd[0], bd[0], (const float*)S[0],
        p.X0, pw[0], p.keys, p.idx, p.M1, cN0, cN0);

    // ===== pool 0 + block 1 =====
    radix_sort(p, p.perm0, cN0);
    fork_side(0);
    k_mapset_v<<<nblk(cN1), TPB, 0, s_side>>>(p.perm0, nullptr, nullptr, p.M1, cN1);
    pdl(k_degdinv, gridA(cN1), TPB, s_side, (const int*)p.rs0, (const int*)p.csr0,
        (const int*)p.perm0, (const int*)p.M1, p.dinv1, cN1);
    pdl(k_mm_pool, nblk((long long)cN1 * 4), TPB, s0, (const float*)p.X0, Wd[1],
        (const int*)p.perm0, (const float*)p.keysOut, p.H, S[1], cN1);
    join_side(0);
    pdl(k_vagg_bn, gridA(cN1), TPB, s0, (const int*)p.rs0, (const int*)p.csr0,
        (const int*)p.perm0, (const int*)p.M1, (const float*)p.dinv1,
        (const float*)p.H, p.Y, S[1], cN1);
    pdl(k_bn_score, 1024, TPB, s0, (const float*)p.Y, gd[1], bd[1], (const float*)S[1],
        p.X1, pw[1], p.keys, p.idx, p.M2, cN0, cN1);

    // ===== pool 1 + block 2 =====
    radix_sort(p, p.perm1, cN1);
    fork_side(1);
    k_mapset_v<<<nblk(cN2), TPB, 0, s_side>>>(p.perm1, p.perm0, p.O2, p.M2, cN2);
    pdl(k_degdinv, gridA(cN2), TPB, s_side, (const int*)p.rs0, (const int*)p.csr0,
        (const int*)p.O2, (const int*)p.M2, p.dinv2, cN2);
    pdl(k_mm_pool, nblk((long long)cN2 * 4), TPB, s0, (const float*)p.X1, Wd[2],
        (const int*)p.perm1, (const float*)p.keysOut, p.H, S[2], cN2);
    join_side(1);
    pdl(k_vagg_bn, gridA(cN2), TPB, s0, (const int*)p.rs0, (const int*)p.csr0,
        (const int*)p.O2, (const int*)p.M2, (const float*)p.dinv2,
        (const float*)p.H, p.Y, S[2], cN2);
    pdl(k_bn_score, 512, TPB, s0, (const float*)p.Y, gd[2], bd[2], (const float*)S[2],
        p.X2, pw[2], p.keys, p.idx, p.M3, cN0, cN2);

    // ===== pool 2 + block 3 =====
    radix_sort(p, p.perm2, cN2);
    fork_side(2);
    k_mapset_v<<<nblk(cN3), TPB, 0, s_side>>>(p.perm2, p.O2, p.O3, p.M3, cN3);
    pdl(k_degdinv, gridA(cN3), TPB, s_side, (const int*)p.rs0, (const int*)p.csr0,
        (const int*)p.O3, (const int*)p.M3, p.dinv3, cN3);
    pdl(k_mm_pool, nblk((long long)cN3 * 4), TPB, s0, (const float*)p.X2, Wd[3],
        (const int*)p.perm2, (const float*)p.keysOut, p.H, S[3], cN3);
    join_side(2);
    pdl(k_vagg_bn, gridA(cN3), TPB, s0, (const int*)p.rs0, (const int*)p.csr0,
        (const int*)p.O3, (const int*)p.M3, (const float*)p.dinv3,
        (const float*)p.H, p.YD3, S[3], cN3);

    // ===== up path =====
    pdl(k_mm_res_bn, nblk((long long)cN2 * 4), TPB, s0, (const float*)p.X2,
        (const float*)p.YD3, (const int*)p.O2, (const int*)p.M3,
        gd[3], bd[3], (const float*)S[3], 1.f / cN3, Wu[0], p.H, S[4], cN2);
    pdl(k_vagg_bn, gridA(cN2), TPB, s0, (const int*)p.rs0, (const int*)p.csr0,
        (const int*)p.O2, (const int*)p.M2, (const float*)p.dinv2,
        (const float*)p.H, p.YU0, S[4], cN2);

    pdl(k_mm_res_bn, nblk((long long)cN1 * 4), TPB, s0, (const float*)p.X1,
        (const float*)p.YU0, (const int*)p.perm0, (const int*)p.M2,
        gu[0], bu[0], (const float*)S[4], 1.f / cN2, Wu[1], p.H, S[5], cN1);
    pdl(k_vagg_bn, gridA(cN1), TPB, s0, (const int*)p.rs0, (const int*)p.csr0,
        (const int*)p.perm0, (const int*)p.M1, (const float*)p.dinv1,
        (const float*)p.H, p.YU1, S[5], cN1);

    pdl(k_mm1_res_bn, nblk(cN0), TPB, s0, (const float*)p.X0, (const float*)p.YU1,
        (const int*)p.M1, gu[1], bu[1], (const float*)S[5], 1.f / cN1,
        Wout, p.h1, cN0);
    pdl(k_csr_final, 2048, TPB, s0, (const int*)p.rs0, (const int*)p.csr0,
        (const float*)p.dinv0_1, (const float*)p.h1, (float*)d_out, cN0);
}

// round 15
// speedup vs baseline: 1.0181x; 1.0181x over previous
#include <cuda_runtime.h>
#include <cub/cub.cuh>

// ---------------------------------------------------------------------------
// Graph U-Net forward — level-0 CSR only; virtual pooled traversal; PDL;
// custom 2-kernel scan (1 elem/thread) replaces cub scan + prep.
// ---------------------------------------------------------------------------
#define cN0 80000
#define cN1 40000
#define cN2 20000
#define cN3 10000
#define cNE 1280000
#define HID 64
#define BN_EPS 1e-5f
#define TPB 256
#define GRIDE 1184
#define SCAN_B 1024
#define SCAN_G ((cN0 + SCAN_B - 1) / SCAN_B)   // 79
#define FULLM 0xffffffffu

// ------------------------- static device scratch ---------------------------
__device__ __align__(16) float g_X0[cN0 * HID];
__device__ __align__(16) float g_X1[cN1 * HID];
__device__ __align__(16) float g_X2[cN2 * HID];
__device__ __align__(16) float g_H [cN0 * HID];
__device__ __align__(16) float g_Y [cN0 * HID];
__device__ __align__(16) float g_YD3[cN3 * HID];
__device__ __align__(16) float g_YU0[cN2 * HID];
__device__ __align__(16) float g_YU1[cN1 * HID];
__device__ int   g_deg[cN0 + 1];
__device__ int   g_part[128];
__device__ int   g_cursor[cN0];
__device__ int   g_rs0[cN0 + 1];
__device__ int   g_csr0[cNE];
__device__ float g_dinv0_2[cN0], g_dinv0_1[cN0];
__device__ float g_dinv1[cN1], g_dinv2[cN2], g_dinv3[cN3];
__device__ float g_keys[cN0], g_keysOut[cN0];
__device__ int   g_idx[cN0];
__device__ int   g_perm0[cN0], g_perm1[cN1], g_perm2[cN2];
__device__ int   g_O2[cN2], g_O3[cN3];
__device__ int   g_M1[cN0], g_M2[cN0], g_M3[cN0];
__device__ float g_statsAll[6 * 128];
__device__ float g_h1[cN0];
__device__ __align__(256) unsigned char g_cubtmp[16 * 1024 * 1024];

// ------------------------------- kernels -----------------------------------
__global__ void k_zero_deg_stats(int* __restrict__ deg, float* __restrict__ stats0, int n) {
    int t = blockIdx.x * blockDim.x + threadIdx.x;
    if (t < n) deg[t] = 0;
    if (t < 128) stats0[t] = 0.f;
}

__global__ void k_hist0(const int* __restrict__ dst, int* __restrict__ deg) {
    cudaGridDependencySynchronize();
    for (int t = blockIdx.x * blockDim.x + threadIdx.x; t < cNE; t += gridDim.x * blockDim.x)
        atomicAdd(&deg[dst[t]], 1);
}

// scan kernel A: per-block (1024-elem) sums
__global__ void __launch_bounds__(SCAN_B)
k_blocksum(const int* __restrict__ deg, int* __restrict__ part, int n) {
    cudaGridDependencySynchronize();
    __shared__ int sw[32];
    int g = blockIdx.x * SCAN_B + threadIdx.x;
    int v = (g < n) ? deg[g] : 0;
    int lane = threadIdx.x & 31, wid = threadIdx.x >> 5;
    #pragma unroll
    for (int o = 16; o > 0; o >>= 1) v += __shfl_xor_sync(FULLM, v, o);
    if (lane == 0) sw[wid] = v;
    __syncthreads();
    if (wid == 0) {
        int s = sw[lane];
        #pragma unroll
        for (int o = 16; o > 0; o >>= 1) s += __shfl_xor_sync(FULLM, s, o);
        if (lane == 0) part[blockIdx.x] = s;
    }
}

// scan kernel B: exclusive scan (1 elem/thread) + rs/cursor/dinv emission
__global__ void __launch_bounds__(SCAN_B)
k_scanprep(const int* __restrict__ deg, const int* __restrict__ part,
           int* __restrict__ rs, int* __restrict__ cursor,
           float* __restrict__ dinvA, float fillA,
           float* __restrict__ dinvB, float fillB, int n) {
    cudaGridDependencySynchronize();
    __shared__ int s_off;
    __shared__ int s_w[32];
    int tid = threadIdx.x, bid = blockIdx.x;
    int lane = tid & 31, wid = tid >> 5;
    // warp 0: sum of preceding block partials
    if (wid == 0) {
        int acc = 0;
        for (int j = lane; j < bid; j += 32) acc += part[j];
        #pragma unroll
        for (int o = 16; o > 0; o >>= 1) acc += __shfl_xor_sync(FULLM, acc, o);
        if (lane == 0) s_off = acc;
    }
    int g = bid * SCAN_B + tid;
    int v = (g < n) ? deg[g] : 0;
    // block inclusive scan
    int inc = v;
    #pragma unroll
    for (int o = 1; o < 32; o <<= 1) {
        int t = __shfl_up_sync(FULLM, inc, o);
        if (lane >= o) inc += t;
    }
    if (lane == 31) s_w[wid] = inc;
    __syncthreads();
    if (wid == 0) {
        int w = s_w[lane];
        #pragma unroll
        for (int o = 1; o < 32; o <<= 1) {
            int t = __shfl_up_sync(FULLM, w, o);
            if (lane >= o) w += t;
        }
        s_w[lane] = w;
    }
    __syncthreads();
    int pre = s_off + (wid ? s_w[wid - 1] : 0) + inc - v;
    if (g < n) {
        rs[g] = pre;
        cursor[g] = pre;
        float df = (float)v;
        dinvA[g] = rsqrtf(df + fillA);
        if (dinvB) dinvB[g] = rsqrtf(df + fillB);
        if (g == n - 1) rs[n] = pre + v;
    }
}

__global__ void k_scatter(const int* __restrict__ srcC, const int* __restrict__ dstC,
                          int* __restrict__ cursor, int* __restrict__ csr) {
    cudaGridDependencySynchronize();
    for (int t = blockIdx.x * blockDim.x + threadIdx.x; t < cNE; t += gridDim.x * blockDim.x) {
        int pos = atomicAdd(&cursor[dstC[t]], 1);
        csr[pos] = srcC[t];
    }
}

__global__ void k_mapset_v(const int* __restrict__ perm, const int* __restrict__ origPrev,
                           int* __restrict__ origOut, int* __restrict__ map, int k) {
    int t = blockIdx.x * blockDim.x + threadIdx.x;
    if (t >= k) return;
    int o = origPrev ? origPrev[perm[t]] : perm[t];
    if (origOut) origOut[t] = o;
    map[o] = t;
}

__global__ void k_degdinv(const int* __restrict__ rs, const int* __restrict__ csr,
                          const int* __restrict__ orig, const int* __restrict__ map,
                          float* __restrict__ dinv, int k) {
    cudaGridDependencySynchronize();
    int lane = threadIdx.x & 31;
    int w = (blockIdx.x * blockDim.x + threadIdx.x) >> 5;
    int nw = (gridDim.x * blockDim.x) >> 5;
    for (int d = w; d < k; d += nw) {
        int o = orig[d];
        int r0 = rs[o], r1 = rs[o + 1];
        int cnt = 0;
        for (int j = r0 + lane; j < r1; j += 32)
            cnt += (map[csr[j]] >= 0) ? 1 : 0;
        #pragma unroll
        for (int off = 16; off > 0; off >>= 1) cnt += __shfl_xor_sync(FULLM, cnt, off);
        if (lane == 0) dinv[d] = rsqrtf((float)cnt + 2.0f);
    }
}

// block 0 fused: 3-channel aggregate over csr0, then 3->64 matmul + BN stats
__global__ void k_agg3_bn(const int* __restrict__ rs, const int* __restrict__ csr,
                          const float* __restrict__ dinv, const float* __restrict__ x,
                          const float* __restrict__ W, float* __restrict__ Y,
                          float* __restrict__ stats, int n) {
    __shared__ float sh[128];
    if (threadIdx.x < 128) sh[threadIdx.x] = 0.f;
    int lane = threadIdx.x & 31;
    float w00 = __ldg(&W[2 * lane]),           w01 = __ldg(&W[2 * lane + 1]);
    float w10 = __ldg(&W[HID + 2 * lane]),     w11 = __ldg(&W[HID + 2 * lane + 1]);
    float w20 = __ldg(&W[2 * HID + 2 * lane]), w21 = __ldg(&W[2 * HID + 2 * lane + 1]);
    cudaGridDependencySynchronize();
    __syncthreads();
    int w = (blockIdx.x * blockDim.x + threadIdx.x) >> 5;
    int nw = (gridDim.x * blockDim.x) >> 5;
    float s0 = 0.f, s1 = 0.f, q0 = 0.f, q1 = 0.f;
    for (int d = w; d < n; d += nw) {
        int r0 = rs[d], r1 = rs[d + 1];
        float ax = 0.f, ay = 0.f, az = 0.f;
        for (int j = r0 + lane; j < r1; j += 32) {
            int s = csr[j];
            float ds = dinv[s];
            const float* xs = x + 3 * (long long)s;
            ax += ds * xs[0];
            ay += ds * xs[1];
            az += ds * xs[2];
        }
        #pragma unroll
        for (int o = 16; o > 0; o >>= 1) {
            ax += __shfl_xor_sync(FULLM, ax, o);
            ay += __shfl_xor_sync(FULLM, ay, o);
            az += __shfl_xor_sync(FULLM, az, o);
        }
        float dd = dinv[d];
        float sf = 2.0f * dd * dd;
        const float* xd = x + 3 * (long long)d;
        float b0 = dd * ax + sf * xd[0];
        float b1 = dd * ay + sf * xd[1];
        float b2 = dd * az + sf * xd[2];
        float y0 = b0 * w00 + b1 * w10 + b2 * w20;
        float y1 = b0 * w01 + b1 * w11 + b2 * w21;
        reinterpret_cast<float2*>(Y)[(long long)d * 32 + lane] = make_float2(y0, y1);
        s0 += y0; s1 += y1; q0 += y0 * y0; q1 += y1 * y1;
    }
    atomicAdd(&sh[2 * lane],      s0);
    atomicAdd(&sh[2 * lane + 1],  s1);
    atomicAdd(&sh[64 + 2 * lane], q0);
    atomicAdd(&sh[65 + 2 * lane], q1);
    __syncthreads();
    if (threadIdx.x < 128) atomicAdd(&stats[threadIdx.x], sh[threadIdx.x]);
}

__global__ void k_mm_pool(const float* __restrict__ X, const float* __restrict__ W,
                          const int* __restrict__ perm, const float* __restrict__ sc,
                          float* __restrict__ H, float* __restrict__ stats, int n) {
    __shared__ float sW[HID * HID];
    for (int i = threadIdx.x; i < HID * HID; i += blockDim.x) sW[i] = W[i];
    cudaGridDependencySynchronize();
    if (blockIdx.x == 0 && threadIdx.x < 128) stats[threadIdx.x] = 0.f;
    __syncthreads();
    int t = blockIdx.x * blockDim.x + threadIdx.x;
    int rg = t >> 4, cg = t & 15;
    if (rg * 4 >= n) return;
    const float* xp[4];
    float s[4];
    #pragma unroll
    for (int i = 0; i < 4; i++) {
        int r = rg * 4 + i;
        xp[i] = X + (long long)perm[r] * HID;
        s[i] = sc[r];
    }
    float acc[4][4];
    #pragma unroll
    for (int i = 0; i < 4; i++)
        #pragma unroll
        for (int j = 0; j < 4; j++) acc[i][j] = 0.f;
    for (int k = 0; k < HID; k++) {
        float4 w = reinterpret_cast<const float4*>(sW)[k * 16 + cg];
        #pragma unroll
        for (int i = 0; i < 4; i++) {
            float xv = xp[i][k] * s[i];
            acc[i][0] += xv * w.x; acc[i][1] += xv * w.y;
            acc[i][2] += xv * w.z; acc[i][3] += xv * w.w;
        }
    }
    #pragma unroll
    for (int i = 0; i < 4; i++)
        reinterpret_cast<float4*>(H)[(long long)(rg * 4 + i) * 16 + cg] =
            make_float4(acc[i][0], acc[i][1], acc[i][2], acc[i][3]);
}

__global__ void k_vagg_bn(const int* __restrict__ rs, const int* __restrict__ csr,
                          const int* __restrict__ orig, const int* __restrict__ map,
                          const float* __restrict__ dinv, const float* __restrict__ H,
                          float* __restrict__ Y, float* __restrict__ stats, int n) {
    __shared__ float sh[128];
    if (threadIdx.x < 128) sh[threadIdx.x] = 0.f;
    cudaGridDependencySynchronize();
    __syncthreads();
    int lane = threadIdx.x & 31;
    int w = (blockIdx.x * blockDim.x + threadIdx.x) >> 5;
    int nw = (gridDim.x * blockDim.x) >> 5;
    float s0 = 0.f, s1 = 0.f, q0 = 0.f, q1 = 0.f;
    for (int d = w; d < n; d += nw) {
        int o = orig[d];
        int r0 = rs[o], r1 = rs[o + 1];
        float dd = dinv[d];
        float a0 = 0.f, a1 = 0.f;
        int j = r0;
        for (; j + 2 <= r1; j += 2) {
            int cA = map[csr[j]];
            int cB = map[csr[j + 1]];
            if (cA >= 0) {
                float cf = dinv[cA] * dd;
                float2 h = reinterpret_cast<const float2*>(H)[(long long)cA * 32 + lane];
                a0 += cf * h.x; a1 += cf * h.y;
            }
            if (cB >= 0) {
                float cf = dinv[cB] * dd;
                float2 h = reinterpret_cast<const float2*>(H)[(long long)cB * 32 + lane];
                a0 += cf * h.x; a1 += cf * h.y;
            }
        }
        if (j < r1) {
            int cA = map[csr[j]];
            if (cA >= 0) {
                float cf = dinv[cA] * dd;
                float2 h = reinterpret_cast<const float2*>(H)[(long long)cA * 32 + lane];
                a0 += cf * h.x; a1 += cf * h.y;
            }
        }
        float2 hd = reinterpret_cast<const float2*>(H)[(long long)d * 32 + lane];
        float sf = 2.0f * dd * dd;
        float y0 = a0 + sf * hd.x;
        float y1 = a1 + sf * hd.y;
        reinterpret_cast<float2*>(Y)[(long long)d * 32 + lane] = make_float2(y0, y1);
        s0 += y0; s1 += y1; q0 += y0 * y0; q1 += y1 * y1;
    }
    atomicAdd(&sh[2 * lane],      s0);
    atomicAdd(&sh[2 * lane + 1],  s1);
    atomicAdd(&sh[64 + 2 * lane], q0);
    atomicAdd(&sh[65 + 2 * lane], q1);
    __syncthreads();
    if (threadIdx.x < 128) atomicAdd(&stats[threadIdx.x], sh[threadIdx.x]);
}

__global__ void k_bn_score(const float* __restrict__ Y, const float* __restrict__ gamma,
                           const float* __restrict__ beta, const float* __restrict__ stats,
                           float* __restrict__ Xo, const float* __restrict__ pw,
                           float* __restrict__ keys, int* __restrict__ idx,
                           int* __restrict__ map, int nMapInit, int n) {
    int gtid = blockIdx.x * blockDim.x + threadIdx.x;
    int stride = gridDim.x * blockDim.x;
    int lane = threadIdx.x & 31;
    float inv_n = 1.f / (float)n;
    float pa = pw[lane], pb = pw[lane + 32];
    float g0 = gamma[lane], g1 = gamma[lane + 32];
    float be0 = beta[lane], be1 = beta[lane + 32];
    float nv = pa * pa + pb * pb;
    #pragma unroll
    for (int o = 16; o > 0; o >>= 1) nv += __shfl_xor_sync(FULLM, nv, o);
    float rn = rsqrtf(nv);
    cudaGridDependencySynchronize();
    float mu0 = stats[lane] * inv_n;
    float var0 = stats[HID + lane] * inv_n - mu0 * mu0;
    float rsA = g0 * rsqrtf(var0 + BN_EPS);
    float mu1 = stats[lane + 32] * inv_n;
    float var1 = stats[HID + lane + 32] * inv_n - mu1 * mu1;
    float rsB = g1 * rsqrtf(var1 + BN_EPS);
    for (int r = gtid >> 5; r < n; r += stride >> 5) {
        float y0 = Y[(long long)r * HID + lane];
        float y1 = Y[(long long)r * HID + lane + 32];
        float x0 = fmaxf(rsA * (y0 - mu0) + be0, 0.f);
        float x1 = fmaxf(rsB * (y1 - mu1) + be1, 0.f);
        Xo[(long long)r * HID + lane] = x0;
        Xo[(long long)r * HID + lane + 32] = x1;
        float v = x0 * pa + x1 * pb;
        #pragma unroll
        for (int o = 16; o > 0; o >>= 1) v += __shfl_xor_sync(FULLM, v, o);
        if (lane == 0) {
            keys[r] = fmaxf(v * rn, 0.f);
            idx[r] = r;
        }
    }
    for (int t = gtid; t < nMapInit; t += stride) map[t] = -1;
}

__global__ void k_mm_res_bn(const float* __restrict__ X, const float* __restrict__ Yup,
                            const int* __restrict__ orig, const int* __restrict__ mapNext,
                            const float* __restrict__ gammaP, const float* __restrict__ betaP,
                            const float* __restrict__ statsP, float inv_np,
                            const float* __restrict__ W,
                            float* __restrict__ H, float* __restrict__ stats, int n) {
    __shared__ float sW[HID * HID];
    __shared__ float sA[HID], sB[HID];
    for (int i = threadIdx.x; i < HID * HID; i += blockDim.x) sW[i] = W[i];
    cudaGridDependencySynchronize();
    if (threadIdx.x < HID) {
        int c = threadIdx.x;
        float mu = statsP[c] * inv_np;
        float var = statsP[HID + c] * inv_np - mu * mu;
        float g = gammaP[c] * rsqrtf(var + BN_EPS);
        sA[c] = g;
        sB[c] = betaP[c] - g * mu;
    }
    if (blockIdx.x == 0 && threadIdx.x < 128) stats[threadIdx.x] = 0.f;
    __syncthreads();
    int t = blockIdx.x * blockDim.x + threadIdx.x;
    int rg = t >> 4, cg = t & 15;
    if (rg * 4 >= n) return;
    const float* xp[4];
    const float* up[4];
    #pragma unroll
    for (int i = 0; i < 4; i++) {
        int r = rg * 4 + i;
        xp[i] = X + (long long)r * HID;
        int m = mapNext[orig ? orig[r] : r];
        up[i] = (m >= 0) ? (Yup + (long long)m * HID) : nullptr;
    }
    float acc[4][4];
    #pragma unroll
    for (int i = 0; i < 4; i++)
        #pragma unroll
        for (int j = 0; j < 4; j++) acc[i][j] = 0.f;
    for (int k = 0; k < HID; k++) {
        float4 wv = reinterpret_cast<const float4*>(sW)[k * 16 + cg];
        float a = sA[k], b = sB[k];
        #pragma unroll
        for (int i = 0; i < 4; i++) {
            float xv = xp[i][k];
            if (up[i]) xv += fmaxf(a * up[i][k] + b, 0.f);
            acc[i][0] += xv * wv.x; acc[i][1] += xv * wv.y;
            acc[i][2] += xv * wv.z; acc[i][3] += xv * wv.w;
        }
    }
    #pragma unroll
    for (int i = 0; i < 4; i++)
        reinterpret_cast<float4*>(H)[(long long)(rg * 4 + i) * 16 + cg] =
            make_float4(acc[i][0], acc[i][1], acc[i][2], acc[i][3]);
}

__global__ void k_mm1_res_bn(const float* __restrict__ X, const float* __restrict__ Yup,
                             const int* __restrict__ mapNext,
                             const float* __restrict__ gammaP, const float* __restrict__ betaP,
                             const float* __restrict__ statsP, float inv_np,
                             const float* __restrict__ W, float* __restrict__ h, int n) {
    __shared__ float sW[HID], sA[HID], sB[HID];
    cudaGridDependencySynchronize();
    if (threadIdx.x < HID) {
        int c = threadIdx.x;
        sW[c] = W[c];
        float mu = statsP[c] * inv_np;
        float var = statsP[HID + c] * inv_np - mu * mu;
        float g = gammaP[c] * rsqrtf(var + BN_EPS);
        sA[c] = g;
        sB[c] = betaP[c] - g * mu;
    }
    __syncthreads();
    int r = blockIdx.x * blockDim.x + threadIdx.x;
    if (r >= n) return;
    int m = mapNext[r];
    const float* xp = X + (long long)r * HID;
    const float* up = (m >= 0) ? (Yup + (long long)m * HID) : nullptr;
    float acc = 0.f;
    #pragma unroll
    for (int k = 0; k < HID; k++) {
        float xv = xp[k];
        if (up) xv += fmaxf(sA[k] * up[k] + sB[k], 0.f);
        acc += xv * sW[k];
    }
    h[r] = acc;
}

__global__ void k_csr_final(const int* __restrict__ rs, const int* __restrict__ csr,
                            const float* __restrict__ dinv, const float* __restrict__ h,
                            float* __restrict__ out, int n) {
    cudaGridDependencySynchronize();
    int lane = threadIdx.x & 31;
    int w = (blockIdx.x * blockDim.x + threadIdx.x) >> 5;
    int nw = (gridDim.x * blockDim.x) >> 5;
    for (int d = w; d < n; d += nw) {
        int r0 = rs[d], r1 = rs[d + 1];
        float acc = 0.f;
        for (int j = r0 + lane; j < r1; j += 32) {
            int s = csr[j];
            acc += dinv[s] * h[s];
        }
        #pragma unroll
        for (int o = 16; o > 0; o >>= 1) acc += __shfl_xor_sync(FULLM, acc, o);
        if (lane == 0) {
            float dd = dinv[d];
            float v = dd * acc + dd * dd * h[d];
            out[d] = 1.f / (1.f + expf(-v));
        }
    }
}

// ------------------------------- host side ---------------------------------
static inline int nblk(long long n) { return (int)((n + TPB - 1) / TPB); }
static inline int gridA(int n) { int g = (n + 7) / 8; return g > 2048 ? 2048 : g; }

template <typename... Args>
static void pdl(void (*kern)(Args...), int grid, int block, cudaStream_t st, Args... args) {
    cudaLaunchConfig_t cfg = {};
    cfg.gridDim = dim3(grid);
    cfg.blockDim = dim3(block);
    cfg.stream = st;
    cudaLaunchAttribute attr[1];
    attr[0].id = cudaLaunchAttributeProgrammaticStreamSerialization;
    attr[0].val.programmaticStreamSerializationAllowed = 1;
    cfg.attrs = attr;
    cfg.numAttrs = 1;
    cudaLaunchKernelEx(&cfg, kern, args...);
}

struct DevPtrs {
    float *X0, *X1, *X2, *H, *Y, *YD3, *YU0, *YU1;
    int *deg, *part, *cursor, *rs0, *csr0;
    float *dinv0_2, *dinv0_1, *dinv1, *dinv2, *dinv3;
    float *keys, *keysOut, *stats, *h1;
    int *idx, *perm0, *perm1, *perm2, *O2, *O3, *M1, *M2, *M3;
    void* cubtmp;
};

#define GETP(sym, field, type) { void* q; cudaGetSymbolAddress(&q, sym); p.field = (type)q; }

static void get_ptrs(DevPtrs& p) {
    GETP(g_X0, X0, float*) GETP(g_X1, X1, float*) GETP(g_X2, X2, float*)
    GETP(g_H, H, float*) GETP(g_Y, Y, float*)
    GETP(g_YD3, YD3, float*) GETP(g_YU0, YU0, float*) GETP(g_YU1, YU1, float*)
    GETP(g_deg, deg, int*) GETP(g_part, part, int*) GETP(g_cursor, cursor, int*)
    GETP(g_rs0, rs0, int*) GETP(g_csr0, csr0, int*)
    GETP(g_dinv0_2, dinv0_2, float*) GETP(g_dinv0_1, dinv0_1, float*)
    GETP(g_dinv1, dinv1, float*) GETP(g_dinv2, dinv2, float*) GETP(g_dinv3, dinv3, float*)
    GETP(g_keys, keys, float*) GETP(g_keysOut, keysOut, float*)
    GETP(g_statsAll, stats, float*) GETP(g_h1, h1, float*)
    GETP(g_idx, idx, int*)
    GETP(g_perm0, perm0, int*) GETP(g_perm1, perm1, int*) GETP(g_perm2, perm2, int*)
    GETP(g_O2, O2, int*) GETP(g_O3, O3, int*)
    GETP(g_M1, M1, int*) GETP(g_M2, M2, int*) GETP(g_M3, M3, int*)
    GETP(g_cubtmp, cubtmp, void*)
}

static cudaStream_t s_side;
static cudaEvent_t  s_evF[3], s_evJ[3];
static bool s_init = false;

static void fork_side(int i) {
    cudaEventRecord(s_evF[i], 0);
    cudaStreamWaitEvent(s_side, s_evF[i], 0);
}
static void join_side(int i) {
    cudaEventRecord(s_evJ[i], s_side);
    cudaStreamWaitEvent(0, s_evJ[i], 0);
}

static void radix_sort(const DevPtrs& p, int* permOut, int n) {
    size_t tb = 0;
    cub::DeviceRadixSort::SortPairsDescending(nullptr, tb, p.keys, p.keysOut,
                                              p.idx, permOut, n, 0, 32, (cudaStream_t)0);
    cub::DeviceRadixSort::SortPairsDescending(p.cubtmp, tb, p.keys, p.keysOut,
                                              p.idx, permOut, n, 0, 32, (cudaStream_t)0);
}

extern "C" void kernel_launch(void* const* d_in, const int* in_sizes, int n_in,
                              void* d_out, int out_size) {
    if (!s_init) {   // first call is the uncaptured correctness run
        cudaStreamCreateWithFlags(&s_side, cudaStreamNonBlocking);
        for (int i = 0; i < 3; i++) {
            cudaEventCreateWithFlags(&s_evF[i], cudaEventDisableTiming);
            cudaEventCreateWithFlags(&s_evJ[i], cudaEventDisableTiming);
        }
        s_init = true;
    }

    const float* x_in = (const float*)d_in[0];
    const int* ei     = (const int*)d_in[1];
    const int* src0 = ei;
    const int* dst0 = ei + cNE;
    const float* Wd[4] = {(const float*)d_in[2],  (const float*)d_in[5],
                          (const float*)d_in[8],  (const float*)d_in[11]};
    const float* gd[4] = {(const float*)d_in[3],  (const float*)d_in[6],
                          (const float*)d_in[9],  (const float*)d_in[12]};
    const float* bd[4] = {(const float*)d_in[4],  (const float*)d_in[7],
                          (const float*)d_in[10], (const float*)d_in[13]};
    const float* pw[3] = {(const float*)d_in[14], (const float*)d_in[15],
                          (const float*)d_in[16]};
    const float* Wu[2] = {(const float*)d_in[17], (const float*)d_in[20]};
    const float* gu[2] = {(const float*)d_in[18], (const float*)d_in[21]};
    const float* bu[2] = {(const float*)d_in[19], (const float*)d_in[22]};
    const float* Wout  = (const float*)d_in[23];

    DevPtrs p;
    get_ptrs(p);
    float* S[6];
    for (int i = 0; i < 6; i++) S[i] = p.stats + i * 128;
    cudaStream_t s0 = 0;

    // ===== level 0: CSR build (custom scan) + fused agg3+mm+BNstats =====
    k_zero_deg_stats<<<nblk(cN0 + 1), TPB>>>(p.deg, S[0], cN0 + 1);
    pdl(k_hist0, GRIDE, TPB, s0, dst0, p.deg);
    pdl(k_blocksum, SCAN_G, SCAN_B, s0, (const int*)p.deg, p.part, cN0);
    pdl(k_scanprep, SCAN_G, SCAN_B, s0, (const int*)p.deg, (const int*)p.part,
        p.rs0, p.cursor, p.dinv0_2, 2.0f, p.dinv0_1, 1.0f, cN0);
    pdl(k_scatter, GRIDE, TPB, s0, src0, dst0, p.cursor, p.csr0);
    pdl(k_agg3_bn, gridA(cN0), TPB, s0, (const int*)p.rs0, (const int*)p.csr0,
        (const float*)p.dinv0_2, x_in, Wd[0], p.Y, S[0], cN0);
    pdl(k_bn_score, 2048, TPB, s0, (const float*)p.Y, gd[0], bd[0], (const float*)S[0],
        p.X0, pw[0], p.keys, p.idx, p.M1, cN0, cN0);

    // ===== pool 0 + block 1 =====
    radix_sort(p, p.perm0, cN0);
    fork_side(0);
    k_mapset_v<<<nblk(cN1), TPB, 0, s_side>>>(p.perm0, nullptr, nullptr, p.M1, cN1);
    pdl(k_degdinv, gridA(cN1), TPB, s_side, (const int*)p.rs0, (const int*)p.csr0,
        (const int*)p.perm0, (const int*)p.M1, p.dinv1, cN1);
    pdl(k_mm_pool, nblk((long long)cN1 * 4), TPB, s0, (const float*)p.X0, Wd[1],
        (const int*)p.perm0, (const float*)p.keysOut, p.H, S[1], cN1);
    join_side(0);
    pdl(k_vagg_bn, gridA(cN1), TPB, s0, (const int*)p.rs0, (const int*)p.csr0,
        (const int*)p.perm0, (const int*)p.M1, (const float*)p.dinv1,
        (const float*)p.H, p.Y, S[1], cN1);
    pdl(k_bn_score, 1024, TPB, s0, (const float*)p.Y, gd[1], bd[1], (const float*)S[1],
        p.X1, pw[1], p.keys, p.idx, p.M2, cN0, cN1);

    // ===== pool 1 + block 2 =====
    radix_sort(p, p.perm1, cN1);
    fork_side(1);
    k_mapset_v<<<nblk(cN2), TPB, 0, s_side>>>(p.perm1, p.perm0, p.O2, p.M2, cN2);
    pdl(k_degdinv, gridA(cN2), TPB, s_side, (const int*)p.rs0, (const int*)p.csr0,
        (const int*)p.O2, (const int*)p.M2, p.dinv2, cN2);
    pdl(k_mm_pool, nblk((long long)cN2 * 4), TPB, s0, (const float*)p.X1, Wd[2],
        (const int*)p.perm1, (const float*)p.keysOut, p.H, S[2], cN2);
    join_side(1);
    pdl(k_vagg_bn, gridA(cN2), TPB, s0, (const int*)p.rs0, (const int*)p.csr0,
        (const int*)p.O2, (const int*)p.M2, (const float*)p.dinv2,
        (const float*)p.H, p.Y, S[2], cN2);
    pdl(k_bn_score, 512, TPB, s0, (const float*)p.Y, gd[2], bd[2], (const float*)S[2],
        p.X2, pw[2], p.keys, p.idx, p.M3, cN0, cN2);

    // ===== pool 2 + block 3 =====
    radix_sort(p, p.perm2, cN2);
    fork_side(2);
    k_mapset_v<<<nblk(cN3), TPB, 0, s_side>>>(p.perm2, p.O2, p.O3, p.M3, cN3);
    pdl(k_degdinv, gridA(cN3), TPB, s_side, (const int*)p.rs0, (const int*)p.csr0,
        (const int*)p.O3, (const int*)p.M3, p.dinv3, cN3);
    pdl(k_mm_pool, nblk((long long)cN3 * 4), TPB, s0, (const float*)p.X2, Wd[3],
        (const int*)p.perm2, (const float*)p.keysOut, p.H, S[3], cN3);
    join_side(2);
    pdl(k_vagg_bn, gridA(cN3), TPB, s0, (const int*)p.rs0, (const int*)p.csr0,
        (const int*)p.O3, (const int*)p.M3, (const float*)p.dinv3,
        (const float*)p.H, p.YD3, S[3], cN3);

    // ===== up path =====
    pdl(k_mm_res_bn, nblk((long long)cN2 * 4), TPB, s0, (const float*)p.X2,
        (const float*)p.YD3, (const int*)p.O2, (const int*)p.M3,
        gd[3], bd[3], (const float*)S[3], 1.f / cN3, Wu[0], p.H, S[4], cN2);
    pdl(k_vagg_bn, gridA(cN2), TPB, s0, (const int*)p.rs0, (const int*)p.csr0,
        (const int*)p.O2, (const int*)p.M2, (const float*)p.dinv2,
        (const float*)p.H, p.YU0, S[4], cN2);

    pdl(k_mm_res_bn, nblk((long long)cN1 * 4), TPB, s0, (const float*)p.X1,
        (const float*)p.YU0, (const int*)p.perm0, (const int*)p.M2,
        gu[0], bu[0], (const float*)S[4], 1.f / cN2, Wu[1], p.H, S[5], cN1);
    pdl(k_vagg_bn, gridA(cN1), TPB, s0, (const int*)p.rs0, (const int*)p.csr0,
        (const int*)p.perm0, (const int*)p.M1, (const float*)p.dinv1,
        (const float*)p.H, p.YU1, S[5], cN1);

    pdl(k_mm1_res_bn, nblk(cN0), TPB, s0, (const float*)p.X0, (const float*)p.YU1,
        (const int*)p.M1, gu[1], bu[1], (const float*)S[5], 1.f / cN1,
        Wout, p.h1, cN0);
    pdl(k_csr_final, 2048, TPB, s0, (const int*)p.rs0, (const int*)p.csr0,
        (const float*)p.dinv0_1, (const float*)p.h1, (float*)d_out, cN0);
}